// round 2
// baseline (speedup 1.0000x reference)
#include <cuda_runtime.h>
#include <math.h>

#define N_NODES 50000
#define N_EDGES 800000
#define HEADS 4
#define HIDD 64
#define NCLS 47
#define NEG 0.2f

// ---------------- static scratch (no allocations allowed) ----------------
__device__ float g_bufA[N_NODES * 256];   // GEMM output features (h), layers 0/1
__device__ float g_bufB[N_NODES * 256];   // aggregated output features
__device__ float g_h2[N_NODES * NCLS];    // layer-2 GEMM output
__device__ float g_el[N_NODES * HEADS];
__device__ float g_er[N_NODES * HEADS];
__device__ int   g_cnt[N_NODES];
__device__ int   g_rowptr[N_NODES + 1];
__device__ int   g_esrc[N_EDGES];

// Buffer selectors (avoid any host-side runtime API; kernels pick the symbol)
#define BUF_A   0
#define BUF_B   1
#define BUF_H2  2
#define BUF_EXT 3

__device__ __forceinline__ float* sel_buf(int sel, float* ext) {
    switch (sel) {
        case BUF_A:  return g_bufA;
        case BUF_B:  return g_bufB;
        case BUF_H2: return g_h2;
        default:     return ext;
    }
}

// ---------------- CSR build (dst-sorted edge list) ----------------
__global__ void zero_cnt_k() {
    int i = blockIdx.x * blockDim.x + threadIdx.x;
    if (i < N_NODES) g_cnt[i] = 0;
}

__global__ void hist_k(const int* __restrict__ dst) {
    int e = blockIdx.x * blockDim.x + threadIdx.x;
    if (e < N_EDGES) atomicAdd(&g_cnt[dst[e]], 1);
}

// single-block exclusive scan over g_cnt -> g_rowptr
__global__ void scan_k() {
    __shared__ int s[1024];
    __shared__ int carry;
    int tid = threadIdx.x;
    if (tid == 0) { carry = 0; g_rowptr[0] = 0; }
    __syncthreads();
    for (int base = 0; base < N_NODES; base += 1024) {
        int i = base + tid;
        int v = (i < N_NODES) ? g_cnt[i] : 0;
        s[tid] = v;
        __syncthreads();
        #pragma unroll
        for (int off = 1; off < 1024; off <<= 1) {
            int t = (tid >= off) ? s[tid - off] : 0;
            __syncthreads();
            s[tid] += t;
            __syncthreads();
        }
        if (i < N_NODES) g_rowptr[i + 1] = carry + s[tid];
        __syncthreads();
        if (tid == 0) carry += s[1023];
        __syncthreads();
    }
}

__global__ void scatter_k(const int* __restrict__ src, const int* __restrict__ dst) {
    int e = blockIdx.x * blockDim.x + threadIdx.x;
    if (e < N_EDGES) {
        int d = dst[e];
        int pos = g_rowptr[d] + atomicAdd(&g_cnt[d], 1);
        g_esrc[pos] = src[e];
    }
}

// ---------------- GEMM: C[n,m] = A[n,256] @ B[256,m] ----------------
#define BM 64
#define BN 64
#define BK 16
__global__ void gemm_k(const float* __restrict__ Aext, int selA, int selC,
                       const float* __restrict__ B, int m) {
    const float* A = (selA == BUF_EXT) ? Aext : (const float*)sel_buf(selA, nullptr);
    float* C = sel_buf(selC, nullptr);

    __shared__ float As[BK][BM];
    __shared__ float Bs[BK][BN + 1];
    int t = threadIdx.x;                 // 256 threads
    int tx = t & 15, ty = t >> 4;
    int row0 = blockIdx.y * BM, col0 = blockIdx.x * BN;
    float acc[4][4] = {};

    int ma = t >> 2;                     // A-load row within tile
    int ka = (t & 3) * 4;                // A-load k offset (float4)

    for (int k0 = 0; k0 < 256; k0 += BK) {
        float4 av = make_float4(0.f, 0.f, 0.f, 0.f);
        int arow = row0 + ma;
        if (arow < N_NODES) av = *(const float4*)(A + (size_t)arow * 256 + k0 + ka);
        As[ka + 0][ma] = av.x;
        As[ka + 1][ma] = av.y;
        As[ka + 2][ma] = av.z;
        As[ka + 3][ma] = av.w;
        #pragma unroll
        for (int i = 0; i < 4; i++) {
            int li = t + i * 256;
            int kb = li >> 6, nb = li & 63;
            int col = col0 + nb;
            Bs[kb][nb] = (col < m) ? B[(size_t)(k0 + kb) * m + col] : 0.f;
        }
        __syncthreads();
        #pragma unroll
        for (int k = 0; k < BK; k++) {
            float a[4], b[4];
            #pragma unroll
            for (int i = 0; i < 4; i++) a[i] = As[k][ty * 4 + i];
            #pragma unroll
            for (int j = 0; j < 4; j++) b[j] = Bs[k][tx * 4 + j];
            #pragma unroll
            for (int i = 0; i < 4; i++)
                #pragma unroll
                for (int j = 0; j < 4; j++)
                    acc[i][j] = fmaf(a[i], b[j], acc[i][j]);
        }
        __syncthreads();
    }
    #pragma unroll
    for (int i = 0; i < 4; i++) {
        int r = row0 + ty * 4 + i;
        if (r < N_NODES) {
            #pragma unroll
            for (int j = 0; j < 4; j++) {
                int c = col0 + tx * 4 + j;
                if (c < m) C[(size_t)r * m + c] = acc[i][j];
            }
        }
    }
}

// ---------------- attention scores: el/er per (node, head) ----------------
template <int H, int D>
__global__ void attn_score_k(int selH,
                             const float* __restrict__ al,
                             const float* __restrict__ ar) {
    const float* hbuf = sel_buf(selH, nullptr);
    int w = (blockIdx.x * blockDim.x + threadIdx.x) >> 5;
    int lane = threadIdx.x & 31;
    if (w >= N_NODES * H) return;
    int n = w / H, hd = w % H;
    float a = 0.f, b = 0.f;
    for (int d = lane; d < D; d += 32) {
        float v = hbuf[(size_t)n * (H * D) + hd * D + d];
        a += v * al[hd * D + d];
        b += v * ar[hd * D + d];
    }
    #pragma unroll
    for (int o = 16; o > 0; o >>= 1) {
        a += __shfl_xor_sync(0xffffffffu, a, o);
        b += __shfl_xor_sync(0xffffffffu, b, o);
    }
    if (lane == 0) {
        g_el[n * H + hd] = a;
        g_er[n * H + hd] = b;
    }
}

// ---------------- per-dst online-softmax aggregation (no atomics) --------
template <int H, int D>
__global__ void agg_k(int selH, int selOut,
                      const float* __restrict__ bias,
                      float* __restrict__ out_ext) {
    const float* hbuf = sel_buf(selH, nullptr);
    float* out = sel_buf(selOut, out_ext);
    int w = (blockIdx.x * blockDim.x + threadIdx.x) >> 5;
    int lane = threadIdx.x & 31;
    if (w >= N_NODES * H) return;
    int n = w / H, hd = w % H;
    int beg = g_rowptr[n], end = g_rowptr[n + 1];
    float ern = g_er[n * H + hd];

    float mx = -INFINITY, den = 0.f, acc0 = 0.f, acc1 = 0.f;
    const int c0 = hd * D + lane;
    const int c1 = hd * D + lane + 32;

    for (int i = beg; i < end; i++) {
        int s = g_esrc[i];
        float e = g_el[s * H + hd] + ern;
        e = (e > 0.f) ? e : NEG * e;
        float mn = fmaxf(mx, e);
        float sc = __expf(mx - mn);   // exp(-inf)=0 on first edge
        float wt = __expf(e - mn);
        den = den * sc + wt;
        const float* hs = hbuf + (size_t)s * (H * D);
        if (lane < D)      acc0 = acc0 * sc + wt * hs[c0];
        if (lane + 32 < D) acc1 = acc1 * sc + wt * hs[c1];
        mx = mn;
    }
    float inv = (end > beg) ? 1.0f / den : 0.f;
    if (lane < D)      out[(size_t)n * (H * D) + c0] = acc0 * inv + bias[c0];
    if (lane + 32 < D) out[(size_t)n * (H * D) + c1] = acc1 * inv + bias[c1];
}

// ---------------- launch (nothing but kernel launches here) ----------------
extern "C" void kernel_launch(void* const* d_in, const int* in_sizes, int n_in,
                              void* d_out, int out_size) {
    const float* x   = (const float*)d_in[0];
    const int*   src = (const int*)d_in[1];
    const int*   dst = (const int*)d_in[2];
    const float* W0  = (const float*)d_in[3];
    const float* al0 = (const float*)d_in[4];
    const float* ar0 = (const float*)d_in[5];
    const float* b0  = (const float*)d_in[6];
    const float* W1  = (const float*)d_in[7];
    const float* al1 = (const float*)d_in[8];
    const float* ar1 = (const float*)d_in[9];
    const float* b1  = (const float*)d_in[10];
    const float* W2  = (const float*)d_in[11];
    const float* al2 = (const float*)d_in[12];
    const float* ar2 = (const float*)d_in[13];
    const float* b2  = (const float*)d_in[14];
    float* out = (float*)d_out;

    const int ZB = (N_NODES + 255) / 256;
    const int EB = (N_EDGES + 255) / 256;
    const int WB4 = (N_NODES * HEADS * 32 + 255) / 256;  // 4-head warp kernels
    const int WB1 = (N_NODES * 1 * 32 + 255) / 256;      // 1-head warp kernels

    // CSR build (dst-major)
    zero_cnt_k<<<ZB, 256>>>();
    hist_k<<<EB, 256>>>(dst);
    scan_k<<<1, 1024>>>();
    zero_cnt_k<<<ZB, 256>>>();
    scatter_k<<<EB, 256>>>(src, dst);

    dim3 g256(4, (N_NODES + BM - 1) / BM);
    dim3 g47(1, (N_NODES + BM - 1) / BM);

    // layer 0: x @ W0 -> bufA ; agg -> bufB
    gemm_k<<<g256, 256>>>(x, BUF_EXT, BUF_A, W0, 256);
    attn_score_k<HEADS, HIDD><<<WB4, 256>>>(BUF_A, al0, ar0);
    agg_k<HEADS, HIDD><<<WB4, 256>>>(BUF_A, BUF_B, b0, nullptr);
    // layer 1: bufB @ W1 -> bufA ; agg -> bufB
    gemm_k<<<g256, 256>>>(nullptr, BUF_B, BUF_A, W1, 256);
    attn_score_k<HEADS, HIDD><<<WB4, 256>>>(BUF_A, al1, ar1);
    agg_k<HEADS, HIDD><<<WB4, 256>>>(BUF_A, BUF_B, b1, nullptr);
    // layer 2: bufB @ W2 -> h2 ; agg (1 head, mean over 1 head = identity) -> out
    gemm_k<<<g47, 256>>>(nullptr, BUF_B, BUF_H2, W2, NCLS);
    attn_score_k<1, NCLS><<<WB1, 256>>>(BUF_H2, al2, ar2);
    agg_k<1, NCLS><<<WB1, 256>>>(BUF_H2, BUF_EXT, b2, out);
}

// round 4
// speedup vs baseline: 1.3001x; 1.3001x over previous
#include <cuda_runtime.h>
#include <math.h>
#include <stdint.h>

#define N_NODES 50000
#define N_EDGES 800000
#define HEADS 4
#define HIDD 64
#define NCLS 47
#define NEG 0.2f

// ---------------- static scratch (no allocations allowed) ----------------
__device__ float g_bufA[N_NODES * 256];   // GEMM output features (h), layers 0/1
__device__ float g_bufB[N_NODES * 256];   // aggregated output features
__device__ float g_h2[N_NODES * NCLS];    // layer-2 GEMM output
__device__ float g_el[N_NODES * HEADS];
__device__ float g_er[N_NODES * HEADS];
__device__ int   g_cnt[N_NODES];
__device__ int   g_rowptr[N_NODES + 1];
__device__ int   g_esrc[N_EDGES];

// Buffer selectors (avoid any host-side runtime API; kernels pick the symbol)
#define BUF_A   0
#define BUF_B   1
#define BUF_H2  2
#define BUF_EXT 3

__device__ __forceinline__ float* sel_buf(int sel, float* ext) {
    switch (sel) {
        case BUF_A:  return g_bufA;
        case BUF_B:  return g_bufB;
        case BUF_H2: return g_h2;
        default:     return ext;
    }
}

// ---------------- CSR build (dst-sorted edge list) ----------------
__global__ void zero_cnt_k() {
    int i = blockIdx.x * blockDim.x + threadIdx.x;
    if (i < N_NODES) g_cnt[i] = 0;
}

__global__ void hist_k(const int* __restrict__ dst) {
    int e = blockIdx.x * blockDim.x + threadIdx.x;
    if (e < N_EDGES) atomicAdd(&g_cnt[dst[e]], 1);
}

// single-block exclusive scan over g_cnt -> g_rowptr
__global__ void scan_k() {
    __shared__ int s[1024];
    __shared__ int carry;
    int tid = threadIdx.x;
    if (tid == 0) { carry = 0; g_rowptr[0] = 0; }
    __syncthreads();
    for (int base = 0; base < N_NODES; base += 1024) {
        int i = base + tid;
        int v = (i < N_NODES) ? g_cnt[i] : 0;
        s[tid] = v;
        __syncthreads();
        #pragma unroll
        for (int off = 1; off < 1024; off <<= 1) {
            int t = (tid >= off) ? s[tid - off] : 0;
            __syncthreads();
            s[tid] += t;
            __syncthreads();
        }
        if (i < N_NODES) g_rowptr[i + 1] = carry + s[tid];
        __syncthreads();
        if (tid == 0) carry += s[1023];
        __syncthreads();
    }
}

__global__ void scatter_k(const int* __restrict__ src, const int* __restrict__ dst) {
    int e = blockIdx.x * blockDim.x + threadIdx.x;
    if (e < N_EDGES) {
        int d = dst[e];
        int pos = g_rowptr[d] + atomicAdd(&g_cnt[d], 1);
        g_esrc[pos] = src[e];
    }
}

// ---------------- tensor-core GEMM: C[n,m] = A[n,256] @ B[256,m] ----------
// 3xTF32 split for near-fp32 accuracy: C = Ah*Bh + Ah*Bl + Al*Bh
// Block tile 128x64, 8 warps (4x2), warp tile 32x32, BK=32, K=256 fixed.

__device__ __forceinline__ void cvt_split(float x, uint32_t& hi, uint32_t& lo) {
    uint32_t h;
    asm("cvt.rna.tf32.f32 %0, %1;" : "=r"(h) : "f"(x));
    hi = h;
    lo = __float_as_uint(x - __uint_as_float(h));
}

__device__ __forceinline__ void mma8(float* c, const uint32_t* a, const uint32_t* b) {
    asm volatile(
        "mma.sync.aligned.m16n8k8.row.col.f32.tf32.tf32.f32 "
        "{%0,%1,%2,%3}, {%4,%5,%6,%7}, {%8,%9}, {%0,%1,%2,%3};"
        : "+f"(c[0]), "+f"(c[1]), "+f"(c[2]), "+f"(c[3])
        : "r"(a[0]), "r"(a[1]), "r"(a[2]), "r"(a[3]), "r"(b[0]), "r"(b[1]));
}

__global__ void __launch_bounds__(256, 2)
gemm_mma_k(const float* __restrict__ Aext, int selA, int selC,
           const float* __restrict__ B, int m) {
    const float* A = (selA == BUF_EXT) ? Aext : (const float*)sel_buf(selA, nullptr);
    float* C = sel_buf(selC, nullptr);

    __shared__ float As[128][36];   // pad 4 -> conflict-free frag reads
    __shared__ float Bs[32][72];    // pad 8 -> conflict-free frag reads

    int t = threadIdx.x;
    int warp = t >> 5, lane = t & 31;
    int wm = warp >> 1, wn = warp & 1;
    int g = lane >> 2, tq = lane & 3;
    int rowBlk = blockIdx.y * 128, colBlk = blockIdx.x * 64;

    float c[2][4][4] = {};

    for (int kt = 0; kt < 256; kt += 32) {
        // load A tile 128x32 (float4, coalesced)
        #pragma unroll
        for (int p = 0; p < 4; p++) {
            int rr = p * 32 + (t >> 3);
            int row = rowBlk + rr;
            int kc = (t & 7) * 4;
            float4 v = make_float4(0.f, 0.f, 0.f, 0.f);
            if (row < N_NODES) v = *(const float4*)(A + (size_t)row * 256 + kt + kc);
            As[rr][kc] = v.x; As[rr][kc + 1] = v.y;
            As[rr][kc + 2] = v.z; As[rr][kc + 3] = v.w;
        }
        // load B tile 32x64 (scalar, guarded for m=47)
        #pragma unroll
        for (int p = 0; p < 2; p++) {
            int kb = p * 16 + (t >> 4);
            int cc = (t & 15) * 4;
            const float* Brow = B + (size_t)(kt + kb) * m;
            #pragma unroll
            for (int i = 0; i < 4; i++) {
                int col = colBlk + cc + i;
                Bs[kb][cc + i] = (col < m) ? Brow[col] : 0.f;
            }
        }
        __syncthreads();

        #pragma unroll
        for (int ks = 0; ks < 32; ks += 8) {
            uint32_t bh[4][2], bl[4][2];
            #pragma unroll
            for (int nt = 0; nt < 4; nt++) {
                int col = wn * 32 + nt * 8 + g;
                cvt_split(Bs[ks + tq][col],     bh[nt][0], bl[nt][0]);
                cvt_split(Bs[ks + tq + 4][col], bh[nt][1], bl[nt][1]);
            }
            #pragma unroll
            for (int mt = 0; mt < 2; mt++) {
                int r0 = wm * 32 + mt * 16 + g;
                uint32_t ah[4], al[4];
                cvt_split(As[r0][ks + tq],         ah[0], al[0]);
                cvt_split(As[r0 + 8][ks + tq],     ah[1], al[1]);
                cvt_split(As[r0][ks + tq + 4],     ah[2], al[2]);
                cvt_split(As[r0 + 8][ks + tq + 4], ah[3], al[3]);
                #pragma unroll
                for (int nt = 0; nt < 4; nt++) {
                    mma8(c[mt][nt], ah, bh[nt]);   // hi*hi
                    mma8(c[mt][nt], ah, bl[nt]);   // hi*lo
                    mma8(c[mt][nt], al, bh[nt]);   // lo*hi
                }
            }
        }
        __syncthreads();
    }

    // store C
    #pragma unroll
    for (int mt = 0; mt < 2; mt++) {
        #pragma unroll
        for (int nt = 0; nt < 4; nt++) {
            int row = rowBlk + wm * 32 + mt * 16 + g;
            int col = colBlk + wn * 32 + nt * 8 + tq * 2;
            if (row < N_NODES) {
                if (col < m)     C[(size_t)row * m + col]     = c[mt][nt][0];
                if (col + 1 < m) C[(size_t)row * m + col + 1] = c[mt][nt][1];
            }
            if (row + 8 < N_NODES) {
                if (col < m)     C[(size_t)(row + 8) * m + col]     = c[mt][nt][2];
                if (col + 1 < m) C[(size_t)(row + 8) * m + col + 1] = c[mt][nt][3];
            }
        }
    }
}

// ---------------- attention scores: el/er per (node, head) ----------------
template <int H, int D>
__global__ void attn_score_k(int selH,
                             const float* __restrict__ al,
                             const float* __restrict__ ar) {
    const float* hbuf = sel_buf(selH, nullptr);
    int w = (blockIdx.x * blockDim.x + threadIdx.x) >> 5;
    int lane = threadIdx.x & 31;
    if (w >= N_NODES * H) return;
    int n = w / H, hd = w % H;
    float a = 0.f, b = 0.f;
    for (int d = lane; d < D; d += 32) {
        float v = hbuf[(size_t)n * (H * D) + hd * D + d];
        a += v * al[hd * D + d];
        b += v * ar[hd * D + d];
    }
    #pragma unroll
    for (int o = 16; o > 0; o >>= 1) {
        a += __shfl_xor_sync(0xffffffffu, a, o);
        b += __shfl_xor_sync(0xffffffffu, b, o);
    }
    if (lane == 0) {
        g_el[n * H + hd] = a;
        g_er[n * H + hd] = b;
    }
}

// ---------------- per-dst online-softmax aggregation (no atomics) --------
template <int H, int D>
__global__ void agg_k(int selH, int selOut,
                      const float* __restrict__ bias,
                      float* __restrict__ out_ext) {
    const float* hbuf = sel_buf(selH, nullptr);
    float* out = sel_buf(selOut, out_ext);
    int w = (blockIdx.x * blockDim.x + threadIdx.x) >> 5;
    int lane = threadIdx.x & 31;
    if (w >= N_NODES * H) return;
    int n = w / H, hd = w % H;
    int beg = g_rowptr[n], end = g_rowptr[n + 1];
    float ern = g_er[n * H + hd];

    float mx = -INFINITY, den = 0.f, acc0 = 0.f, acc1 = 0.f;
    const int c0 = hd * D + lane;
    const int c1 = hd * D + lane + 32;

    for (int i = beg; i < end; i++) {
        int s = g_esrc[i];
        float e = g_el[s * H + hd] + ern;
        e = (e > 0.f) ? e : NEG * e;
        float mn = fmaxf(mx, e);
        float sc = __expf(mx - mn);   // exp(-inf)=0 on first edge
        float wt = __expf(e - mn);
        den = den * sc + wt;
        const float* hs = hbuf + (size_t)s * (H * D);
        if (lane < D)      acc0 = acc0 * sc + wt * hs[c0];
        if (lane + 32 < D) acc1 = acc1 * sc + wt * hs[c1];
        mx = mn;
    }
    float inv = (end > beg) ? 1.0f / den : 0.f;
    if (lane < D)      out[(size_t)n * (H * D) + c0] = acc0 * inv + bias[c0];
    if (lane + 32 < D) out[(size_t)n * (H * D) + c1] = acc1 * inv + bias[c1];
}

// ---------------- launch (nothing but kernel launches here) ----------------
extern "C" void kernel_launch(void* const* d_in, const int* in_sizes, int n_in,
                              void* d_out, int out_size) {
    const float* x   = (const float*)d_in[0];
    const int*   src = (const int*)d_in[1];
    const int*   dst = (const int*)d_in[2];
    const float* W0  = (const float*)d_in[3];
    const float* al0 = (const float*)d_in[4];
    const float* ar0 = (const float*)d_in[5];
    const float* b0  = (const float*)d_in[6];
    const float* W1  = (const float*)d_in[7];
    const float* al1 = (const float*)d_in[8];
    const float* ar1 = (const float*)d_in[9];
    const float* b1  = (const float*)d_in[10];
    const float* W2  = (const float*)d_in[11];
    const float* al2 = (const float*)d_in[12];
    const float* ar2 = (const float*)d_in[13];
    const float* b2  = (const float*)d_in[14];
    float* out = (float*)d_out;

    const int ZB = (N_NODES + 255) / 256;
    const int EB = (N_EDGES + 255) / 256;
    const int WB4 = (N_NODES * HEADS * 32 + 255) / 256;  // 4-head warp kernels
    const int WB1 = (N_NODES * 1 * 32 + 255) / 256;      // 1-head warp kernels

    // CSR build (dst-major)
    zero_cnt_k<<<ZB, 256>>>();
    hist_k<<<EB, 256>>>(dst);
    scan_k<<<1, 1024>>>();
    zero_cnt_k<<<ZB, 256>>>();
    scatter_k<<<EB, 256>>>(src, dst);

    dim3 g256(4, (N_NODES + 127) / 128);
    dim3 g47(1, (N_NODES + 127) / 128);

    // layer 0: x @ W0 -> bufA ; agg -> bufB
    gemm_mma_k<<<g256, 256>>>(x, BUF_EXT, BUF_A, W0, 256);
    attn_score_k<HEADS, HIDD><<<WB4, 256>>>(BUF_A, al0, ar0);
    agg_k<HEADS, HIDD><<<WB4, 256>>>(BUF_A, BUF_B, b0, nullptr);
    // layer 1: bufB @ W1 -> bufA ; agg -> bufB
    gemm_mma_k<<<g256, 256>>>(nullptr, BUF_B, BUF_A, W1, 256);
    attn_score_k<HEADS, HIDD><<<WB4, 256>>>(BUF_A, al1, ar1);
    agg_k<HEADS, HIDD><<<WB4, 256>>>(BUF_A, BUF_B, b1, nullptr);
    // layer 2: bufB @ W2 -> h2 ; agg (1 head, mean over 1 head = identity) -> out
    gemm_mma_k<<<g47, 256>>>(nullptr, BUF_B, BUF_H2, W2, NCLS);
    attn_score_k<1, NCLS><<<WB1, 256>>>(BUF_H2, al2, ar2);
    agg_k<1, NCLS><<<WB1, 256>>>(BUF_H2, BUF_EXT, b2, out);
}